// round 2
// baseline (speedup 1.0000x reference)
#include <cuda_runtime.h>
#include <cstdint>

// Problem constants (fixed-shape variant)
#define BS 4
#define NQ 10000
#define NH 8
#define HD 32
#define NP 4
#define SH 100
#define SW 100

// value layout: [b][pix][h][d], pix = y*SW + x
// loc layout:   [b][q][h][0][p][2]  -> ((warp)*NP + p)*2
// aw layout:    [b][q][h][0][p]     -> warp*NP + p
// out layout:   [b][q][h*HD + d]    -> warp*HD + lane
// with warp = (b*NQ + q)*NH + h

__global__ __launch_bounds__(256) void deform_attn_kernel(
    const float* __restrict__ value,
    const float* __restrict__ loc,
    const float* __restrict__ aw,
    float* __restrict__ out)
{
    const int gtid = blockIdx.x * blockDim.x + threadIdx.x;
    const int warp = gtid >> 5;
    const int lane = gtid & 31;
    if (warp >= BS * NQ * NH) return;

    const int h = warp & (NH - 1);
    const int b = warp / (NQ * NH);

    // base pointer for this (b, h, lane): add pix*NH*HD to index pixels
    const float* vbase = value + (size_t)b * (SH * SW * NH * HD) + h * HD + lane;
    const float2* lptr = reinterpret_cast<const float2*>(loc) + (size_t)warp * NP;
    const float* wptr = aw + (size_t)warp * NP;

    float acc = 0.0f;

#pragma unroll
    for (int p = 0; p < NP; ++p) {
        const float2 l = __ldg(lptr + p);
        const float w = __ldg(wptr + p);

        // grid = 2*loc - 1; unnormalize align_corners=False:
        // x = (grid_x + 1) * W/2 - 0.5  ==  loc_x * W - 0.5
        const float x = l.x * (float)SW - 0.5f;
        const float y = l.y * (float)SH - 0.5f;

        const float xf = floorf(x);
        const float yf = floorf(y);
        const int x0 = (int)xf;
        const int y0 = (int)yf;
        const float tx = x - xf;
        const float ty = y - yf;

        const float w00 = (1.0f - tx) * (1.0f - ty) * w;
        const float w10 = tx * (1.0f - ty) * w;
        const float w01 = (1.0f - tx) * ty * w;
        const float w11 = tx * ty * w;

        const bool vx0 = (x0 >= 0) && (x0 < SW);
        const bool vx1 = (x0 + 1 >= 0) && (x0 + 1 < SW);
        const bool vy0 = (y0 >= 0) && (y0 < SH);
        const bool vy1 = (y0 + 1 >= 0) && (y0 + 1 < SH);

        const int pixstride = NH * HD;  // 256 floats between adjacent pixels

        if (vy0) {
            const float* row = vbase + (size_t)y0 * SW * pixstride;
            if (vx0) acc += w00 * __ldg(row + (size_t)x0 * pixstride);
            if (vx1) acc += w10 * __ldg(row + (size_t)(x0 + 1) * pixstride);
        }
        if (vy1) {
            const float* row = vbase + (size_t)(y0 + 1) * SW * pixstride;
            if (vx0) acc += w01 * __ldg(row + (size_t)x0 * pixstride);
            if (vx1) acc += w11 * __ldg(row + (size_t)(x0 + 1) * pixstride);
        }
    }

    out[(size_t)warp * HD + lane] = acc;
}

extern "C" void kernel_launch(void* const* d_in, const int* in_sizes, int n_in,
                              void* d_out, int out_size)
{
    const float* value = (const float*)d_in[0];
    // d_in[1] = value_spatial_shapes (int64), unused in fixed-size variant
    const float* loc = (const float*)d_in[2];
    const float* aw = (const float*)d_in[3];
    float* out = (float*)d_out;

    const int total_warps = BS * NQ * NH;            // 320000
    const int threads = 256;                          // 8 warps per block
    const int blocks = (total_warps * 32 + threads - 1) / threads;  // 40000

    deform_attn_kernel<<<blocks, threads>>>(value, loc, aw, out);
}